// round 9
// baseline (speedup 1.0000x reference)
#include <cuda_runtime.h>
#include <cuda_bf16.h>

// FastGaussian2D: tile-binned 2D gaussian splat render, inlined-payload bins,
// software-pipelined render loop (depth-2 prefetch breaks the lockstep
// load->use stall that capped issue at ~40% in R8).
// P pixels (256x256 = 512 tiles of 16x8), N=2048 gaussians.
// out[p] = clip(sum_n alpha*color / max(sum alpha,1e-8), 0, 1)
//
// Two launches:
//   fg_bin:    warp per gaussian. Computes constants, walks the tile bbox of
//              the conservative cull ellipse, appends full payloads (2xfloat4)
//              into per-tile lists.
//   fg_render: block per tile (8 warps stride the list by 8, each iteration
//              consumes the pair prefetched 2 iterations earlier). f32x2
//              packed eval + ex2.approx; block smem reduction; finalize +
//              write d_out directly. Zeroes its tile's counter afterwards so
//              the "counts zero at bin start" invariant holds every replay.
//
// Cull safety: dropped per-pixel alpha <= N * w_max * 2^-40 ~ 3e-10 absolute.

#define IMG_W 256
#define TILE_W 16
#define TILE_H 8
#define NTILES_X 16
#define NTILES_Y 32
#define NTILES 512
#define MAX_N 2048
#define LOG2E 1.4426950408889634f
#define PI_F  3.14159265358979323846f
#define THR_LOG2 -40.0f

typedef unsigned long long ull;

__device__ int    g_counts[NTILES];            // zero-init; re-zeroed by render
__device__ float4 gLA[NTILES * MAX_N];         // per-tile inlined {px,py,naxl,nayl}
__device__ float4 gLW[NTILES * MAX_N];         // per-tile inlined {wr,wg,wb,c}

__device__ __forceinline__ ull packf(float a, float b) {
    return (ull)__float_as_uint(a) | ((ull)__float_as_uint(b) << 32);
}
__device__ __forceinline__ float lowf(ull v)  { return __uint_as_float((unsigned)v); }
__device__ __forceinline__ float highf(ull v) { return __uint_as_float((unsigned)(v >> 32)); }

__device__ __forceinline__ ull add2(ull a, ull b) {
    ull d; asm("add.rn.f32x2 %0, %1, %2;" : "=l"(d) : "l"(a), "l"(b)); return d;
}
__device__ __forceinline__ ull mul2(ull a, ull b) {
    ull d; asm("mul.rn.f32x2 %0, %1, %2;" : "=l"(d) : "l"(a), "l"(b)); return d;
}
__device__ __forceinline__ ull fma2(ull a, ull b, ull c) {
    ull d; asm("fma.rn.f32x2 %0, %1, %2, %3;" : "=l"(d) : "l"(a), "l"(b), "l"(c)); return d;
}
__device__ __forceinline__ float ex2f(float x) {
    float y; asm("ex2.approx.ftz.f32 %0, %1;" : "=f"(y) : "f"(x)); return y;
}

// ---------------------------------------------------------------- bin
__global__ void fg_bin(const float* __restrict__ pos,
                       const float* __restrict__ lsc,
                       const float* __restrict__ col,
                       const float* __restrict__ lop, int N) {
    const int g    = (blockIdx.x * blockDim.x + threadIdx.x) >> 5;
    const int lane = threadIdx.x & 31;
    if (g >= N) return;

    const float px = pos[2*g], py = pos[2*g+1];
    const float sx = fmaxf(expf(lsc[2*g]),   0.1f);
    const float sy = fmaxf(expf(lsc[2*g+1]), 0.1f);
    const float opac = expf(lop[g]);
    const float c = opac / (2.0f * PI_F * sx * sy);
    const float naxl = -0.5f * LOG2E / (sx * sx);
    const float nayl = -0.5f * LOG2E / (sy * sy);

    const float4 A = make_float4(px, py, naxl, nayl);
    const float4 W = make_float4(c * col[3*g], c * col[3*g+1], c * col[3*g+2], c);

    // conservative cull radii: naxl * r^2 = THR (both negative)
    const float rx = sqrtf(THR_LOG2 / naxl);
    const float ry = sqrtf(THR_LOG2 / nayl);

    int tx0 = max(0,            (int)floorf((px - rx) * (1.0f/TILE_W)));
    int tx1 = min(NTILES_X - 1, (int)floorf((px + rx) * (1.0f/TILE_W)));
    int ty0 = max(0,            (int)floorf((py - ry) * (1.0f/TILE_H)));
    int ty1 = min(NTILES_Y - 1, (int)floorf((py + ry) * (1.0f/TILE_H)));
    if (tx1 < tx0 || ty1 < ty0) return;

    const int wbb = tx1 - tx0 + 1;
    const int nt  = wbb * (ty1 - ty0 + 1);

    for (int i = lane; i < nt; i += 32) {
        const int tx = tx0 + i % wbb;
        const int ty = ty0 + i / wbb;
        const float mx = fmaxf(fabsf((float)(tx * TILE_W) + 7.5f - px) - 7.5f, 0.0f);
        const float my = fmaxf(fabsf((float)(ty * TILE_H) + 3.5f - py) - 3.5f, 0.0f);
        if (naxl * (mx * mx) + nayl * (my * my) >= THR_LOG2) {
            const int t = ty * NTILES_X + tx;
            const int slot = atomicAdd(&g_counts[t], 1);   // slot < N by construction
            gLA[t * MAX_N + slot] = A;
            gLW[t * MAX_N + slot] = W;
        }
    }
}

// ---------------------------------------------------------------- render
__global__ void __launch_bounds__(256, 4)
fg_render(float* __restrict__ out, int P) {
    __shared__ float sred[8 * 512];   // 16 KB: 8 warps x (32 lanes x 16 floats)

    const int tile = blockIdx.x;
    const int warp = threadIdx.x >> 5;
    const int lane = threadIdx.x & 31;

    const int x0 = (tile & (NTILES_X - 1)) * TILE_W;
    const int y0 = (tile >> 4) * TILE_H;

    const float cy = (float)(y0 + (lane >> 2));
    const float xf = (float)(x0 + (lane & 3) * 4);
    const ull cx0 = packf(xf,        xf + 1.0f);
    const ull cx1 = packf(xf + 2.0f, xf + 3.0f);

    const int count = g_counts[tile];
    const int base  = tile * MAX_N;
    const int cm1   = max(count - 1, 0);   // clamp target for always-legal loads

    ull aR0 = 0, aR1 = 0, aG0 = 0, aG1 = 0;
    ull aB0 = 0, aB1 = 0, aA0 = 0, aA1 = 0;

    // depth-2 software pipeline: iteration j consumes the pair prefetched two
    // iterations ago and immediately prefetches j+16 into the freed slot.
    // Clamped indices make every load unconditional (garbage data is never
    // consumed because the loop guard uses the true j).
    float4 bA[2], bW[2];
    {
        const int i0 = min(warp,     cm1);
        const int i1 = min(warp + 8, cm1);
        bA[0] = gLA[base + i0];  bW[0] = gLW[base + i0];
        bA[1] = gLA[base + i1];  bW[1] = gLW[base + i1];
    }

    int par = 0;
    #pragma unroll 2
    for (int j = warp; j < count; j += 8) {
        const float4 A = bA[par];
        const float4 W = bW[par];
        const int jn = min(j + 16, cm1);
        bA[par] = gLA[base + jn];
        bW[par] = gLW[base + jn];
        par ^= 1;

        const float dy = cy - A.y;
        const float ey = (dy * dy) * A.w;            // nayl*dy^2 (log2-scaled)
        const ull ey2   = packf(ey, ey);
        const ull npx2  = packf(-A.x, -A.x);
        const ull naxl2 = packf(A.z, A.z);

        const ull d0 = add2(cx0, npx2);              // dx
        const ull d1 = add2(cx1, npx2);
        const ull e0 = fma2(mul2(d0, d0), naxl2, ey2);   // naxl*dx^2 + ey
        const ull e1 = fma2(mul2(d1, d1), naxl2, ey2);

        const ull x0p = packf(ex2f(lowf(e0)), ex2f(highf(e0)));
        const ull x1p = packf(ex2f(lowf(e1)), ex2f(highf(e1)));

        const ull wR = packf(W.x, W.x);
        const ull wG = packf(W.y, W.y);
        const ull wB = packf(W.z, W.z);
        const ull wA = packf(W.w, W.w);

        aR0 = fma2(x0p, wR, aR0);  aR1 = fma2(x1p, wR, aR1);
        aG0 = fma2(x0p, wG, aG0);  aG1 = fma2(x1p, wG, aG1);
        aB0 = fma2(x0p, wB, aB0);  aB1 = fma2(x1p, wB, aB1);
        aA0 = fma2(x0p, wA, aA0);  aA1 = fma2(x1p, wA, aA1);
    }

    // per-lane layout k = c*4 + j : channel c in {R,G,B,A}, pixel j in 0..3
    float vals[16];
    vals[ 0] = lowf(aR0); vals[ 1] = highf(aR0); vals[ 2] = lowf(aR1); vals[ 3] = highf(aR1);
    vals[ 4] = lowf(aG0); vals[ 5] = highf(aG0); vals[ 6] = lowf(aG1); vals[ 7] = highf(aG1);
    vals[ 8] = lowf(aB0); vals[ 9] = highf(aB0); vals[10] = lowf(aB1); vals[11] = highf(aB1);
    vals[12] = lowf(aA0); vals[13] = highf(aA0); vals[14] = lowf(aA1); vals[15] = highf(aA1);

    float* dst = &sred[warp * 512 + lane * 16];
    #pragma unroll
    for (int k = 0; k < 16; ++k) dst[k] = vals[k];
    __syncthreads();

    // restore the "counts zero at bin start" invariant for the next replay
    if (threadIdx.x == 0) g_counts[tile] = 0;

    // reduce 8 warp-copies of 512 floats: each thread sums 2 slots
    const int i0 = threadIdx.x;
    const int i1 = threadIdx.x + 256;
    float s0 = 0.f, s1 = 0.f;
    #pragma unroll
    for (int w = 0; w < 8; ++w) {
        s0 += sred[w * 512 + i0];
        s1 += sred[w * 512 + i1];
    }
    __syncthreads();
    sred[i0] = s0;
    sred[i1] = s1;
    __syncthreads();

    // finalize: threads 0..127 each own one pixel of the tile
    if (threadIdx.x < 128) {
        const int p = threadIdx.x;        // = l*4 + j
        const int l = p >> 2;
        const int j = p & 3;
        const float r = sred[l * 16 +  0 + j];
        const float g = sred[l * 16 +  4 + j];
        const float b = sred[l * 16 +  8 + j];
        const float a = sred[l * 16 + 12 + j];
        const float inv = 1.0f / fmaxf(a, 1e-8f);
        const int ppx = x0 + (l & 3) * 4 + j;
        const int ppy = y0 + (l >> 2);
        const int pp  = ppy * IMG_W + ppx;
        if (pp < P) {
            out[3*pp + 0] = __saturatef(r * inv);
            out[3*pp + 1] = __saturatef(g * inv);
            out[3*pp + 2] = __saturatef(b * inv);
        }
    }
}

// ---------------------------------------------------------------- launch
extern "C" void kernel_launch(void* const* d_in, const int* in_sizes, int n_in,
                              void* d_out, int out_size) {
    const float* pos = (const float*)d_in[1];
    const float* lsc = (const float*)d_in[2];
    const float* col = (const float*)d_in[3];
    const float* lop = (const float*)d_in[4];
    float* out = (float*)d_out;

    int N = in_sizes[1] / 2;
    int P = out_size / 3;
    if (N > MAX_N) N = MAX_N;

    const int bin_threads = N * 32;                       // one warp per gaussian
    fg_bin<<<(bin_threads + 255) / 256, 256>>>(pos, lsc, col, lop, N);
    fg_render<<<NTILES, 256>>>(out, P);
}

// round 10
// speedup vs baseline: 1.0052x; 1.0052x over previous
#include <cuda_runtime.h>
#include <cuda_bf16.h>

// FastGaussian2D: tile-binned 2D gaussian splat render.
// P pixels (256x256 = 512 tiles of 16x8), N=2048 gaussians.
// out[p] = clip(sum_n alpha*color / max(sum alpha,1e-8), 0, 1)
//
// R10: per-warp CONTIGUOUS list chunks (spatial locality -> L1 hits,
// de-correlated warp stalls) + bin-side pre-duplicated packed payloads
// (no packing MOVs in the hot loop).
//
// Two launches:
//   fg_bin:    warp per gaussian. Computes constants, walks the tile bbox of
//              the conservative cull ellipse, appends render-ready packed
//              payloads into per-tile lists.
//   fg_render: block per tile; warp w processes list slice [cnt*w/8,cnt*(w+1)/8).
//              f32x2 packed eval + ex2.approx; block smem reduction; finalize
//              + write d_out directly. Zeroes its tile's counter afterwards so
//              the "counts zero at bin start" invariant holds every replay.
//
// Cull safety: dropped per-pixel alpha <= N * w_max * 2^-40 ~ 3e-10 absolute.

#define IMG_W 256
#define TILE_W 16
#define TILE_H 8
#define NTILES_X 16
#define NTILES_Y 32
#define NTILES 512
#define MAX_N 2048
#define LOG2E 1.4426950408889634f
#define PI_F  3.14159265358979323846f
#define THR_LOG2 -40.0f

typedef unsigned long long ull;

__device__ int        g_counts[NTILES];          // zero-init; re-zeroed by render
__device__ ulonglong2 gP0 [NTILES * MAX_N];      // {(-px,-px), (naxl,naxl)}
__device__ ulonglong2 gW12[NTILES * MAX_N];      // {(wr,wr), (wg,wg)}
__device__ ulonglong2 gW34[NTILES * MAX_N];      // {(wb,wb), (wa,wa)}
__device__ float2     gPY [NTILES * MAX_N];      // {py, nayl}

__device__ __forceinline__ ull packf(float a, float b) {
    return (ull)__float_as_uint(a) | ((ull)__float_as_uint(b) << 32);
}
__device__ __forceinline__ float lowf(ull v)  { return __uint_as_float((unsigned)v); }
__device__ __forceinline__ float highf(ull v) { return __uint_as_float((unsigned)(v >> 32)); }

__device__ __forceinline__ ull add2(ull a, ull b) {
    ull d; asm("add.rn.f32x2 %0, %1, %2;" : "=l"(d) : "l"(a), "l"(b)); return d;
}
__device__ __forceinline__ ull mul2(ull a, ull b) {
    ull d; asm("mul.rn.f32x2 %0, %1, %2;" : "=l"(d) : "l"(a), "l"(b)); return d;
}
__device__ __forceinline__ ull fma2(ull a, ull b, ull c) {
    ull d; asm("fma.rn.f32x2 %0, %1, %2, %3;" : "=l"(d) : "l"(a), "l"(b), "l"(c)); return d;
}
__device__ __forceinline__ float ex2f(float x) {
    float y; asm("ex2.approx.ftz.f32 %0, %1;" : "=f"(y) : "f"(x)); return y;
}

// ---------------------------------------------------------------- bin
__global__ void fg_bin(const float* __restrict__ pos,
                       const float* __restrict__ lsc,
                       const float* __restrict__ col,
                       const float* __restrict__ lop, int N) {
    const int g    = (blockIdx.x * blockDim.x + threadIdx.x) >> 5;
    const int lane = threadIdx.x & 31;
    if (g >= N) return;

    const float px = pos[2*g], py = pos[2*g+1];
    const float sx = fmaxf(expf(lsc[2*g]),   0.1f);
    const float sy = fmaxf(expf(lsc[2*g+1]), 0.1f);
    const float opac = expf(lop[g]);
    const float c = opac / (2.0f * PI_F * sx * sy);
    const float naxl = -0.5f * LOG2E / (sx * sx);
    const float nayl = -0.5f * LOG2E / (sy * sy);

    const ulonglong2 P0  = make_ulonglong2(packf(-px, -px), packf(naxl, naxl));
    const float wr = c * col[3*g], wg = c * col[3*g+1], wb = c * col[3*g+2];
    const ulonglong2 W12 = make_ulonglong2(packf(wr, wr), packf(wg, wg));
    const ulonglong2 W34 = make_ulonglong2(packf(wb, wb), packf(c,  c));
    const float2 PY = make_float2(py, nayl);

    // conservative cull radii: naxl * r^2 = THR (both negative)
    const float rx = sqrtf(THR_LOG2 / naxl);
    const float ry = sqrtf(THR_LOG2 / nayl);

    int tx0 = max(0,            (int)floorf((px - rx) * (1.0f/TILE_W)));
    int tx1 = min(NTILES_X - 1, (int)floorf((px + rx) * (1.0f/TILE_W)));
    int ty0 = max(0,            (int)floorf((py - ry) * (1.0f/TILE_H)));
    int ty1 = min(NTILES_Y - 1, (int)floorf((py + ry) * (1.0f/TILE_H)));
    if (tx1 < tx0 || ty1 < ty0) return;

    const int wbb = tx1 - tx0 + 1;
    const int nt  = wbb * (ty1 - ty0 + 1);

    for (int i = lane; i < nt; i += 32) {
        const int tx = tx0 + i % wbb;
        const int ty = ty0 + i / wbb;
        const float mx = fmaxf(fabsf((float)(tx * TILE_W) + 7.5f - px) - 7.5f, 0.0f);
        const float my = fmaxf(fabsf((float)(ty * TILE_H) + 3.5f - py) - 3.5f, 0.0f);
        if (naxl * (mx * mx) + nayl * (my * my) >= THR_LOG2) {
            const int t = ty * NTILES_X + tx;
            const int slot = atomicAdd(&g_counts[t], 1);   // slot < N by construction
            const int idx = t * MAX_N + slot;
            gP0 [idx] = P0;
            gW12[idx] = W12;
            gW34[idx] = W34;
            gPY [idx] = PY;
        }
    }
}

// ---------------------------------------------------------------- render
__global__ void __launch_bounds__(256, 4)
fg_render(float* __restrict__ out, int P) {
    __shared__ float sred[8 * 512];   // 16 KB: 8 warps x (32 lanes x 16 floats)

    const int tile = blockIdx.x;
    const int warp = threadIdx.x >> 5;
    const int lane = threadIdx.x & 31;

    const int x0 = (tile & (NTILES_X - 1)) * TILE_W;
    const int y0 = (tile >> 4) * TILE_H;

    const float cy = (float)(y0 + (lane >> 2));
    const float xf = (float)(x0 + (lane & 3) * 4);
    const ull cx0 = packf(xf,        xf + 1.0f);
    const ull cx1 = packf(xf + 2.0f, xf + 3.0f);

    const int count = g_counts[tile];
    const int base  = tile * MAX_N;

    // contiguous per-warp slice: consecutive iterations hit adjacent 16B ->
    // L1-resident lines; warps stream disjoint regions (de-correlated stalls)
    const int j0 = (count *  warp     ) >> 3;
    const int j1 = (count * (warp + 1)) >> 3;

    ull aR0 = 0, aR1 = 0, aG0 = 0, aG1 = 0;
    ull aB0 = 0, aB1 = 0, aA0 = 0, aA1 = 0;

    #pragma unroll 4
    for (int j = j0; j < j1; ++j) {
        const int idx = base + j;
        const ulonglong2 c1  = gP0 [idx];   // (-px,-px), (naxl,naxl)
        const float2     yv  = gPY [idx];   // py, nayl
        const ulonglong2 w12 = gW12[idx];   // (wr,wr), (wg,wg)
        const ulonglong2 w34 = gW34[idx];   // (wb,wb), (wa,wa)

        const float dy = cy - yv.x;
        const float ey = (dy * dy) * yv.y;            // nayl*dy^2 (log2-scaled)
        const ull ey2 = packf(ey, ey);

        const ull d0 = add2(cx0, c1.x);               // dx
        const ull d1 = add2(cx1, c1.x);
        const ull e0 = fma2(mul2(d0, d0), c1.y, ey2); // naxl*dx^2 + ey
        const ull e1 = fma2(mul2(d1, d1), c1.y, ey2);

        const ull x0p = packf(ex2f(lowf(e0)), ex2f(highf(e0)));
        const ull x1p = packf(ex2f(lowf(e1)), ex2f(highf(e1)));

        aR0 = fma2(x0p, w12.x, aR0);  aR1 = fma2(x1p, w12.x, aR1);
        aG0 = fma2(x0p, w12.y, aG0);  aG1 = fma2(x1p, w12.y, aG1);
        aB0 = fma2(x0p, w34.x, aB0);  aB1 = fma2(x1p, w34.x, aB1);
        aA0 = fma2(x0p, w34.y, aA0);  aA1 = fma2(x1p, w34.y, aA1);
    }

    // per-lane layout k = c*4 + j : channel c in {R,G,B,A}, pixel j in 0..3
    float vals[16];
    vals[ 0] = lowf(aR0); vals[ 1] = highf(aR0); vals[ 2] = lowf(aR1); vals[ 3] = highf(aR1);
    vals[ 4] = lowf(aG0); vals[ 5] = highf(aG0); vals[ 6] = lowf(aG1); vals[ 7] = highf(aG1);
    vals[ 8] = lowf(aB0); vals[ 9] = highf(aB0); vals[10] = lowf(aB1); vals[11] = highf(aB1);
    vals[12] = lowf(aA0); vals[13] = highf(aA0); vals[14] = lowf(aA1); vals[15] = highf(aA1);

    float* dst = &sred[warp * 512 + lane * 16];
    #pragma unroll
    for (int k = 0; k < 16; ++k) dst[k] = vals[k];
    __syncthreads();

    // restore the "counts zero at bin start" invariant for the next replay
    if (threadIdx.x == 0) g_counts[tile] = 0;

    // reduce 8 warp-copies of 512 floats: each thread sums 2 slots
    const int i0 = threadIdx.x;
    const int i1 = threadIdx.x + 256;
    float s0 = 0.f, s1 = 0.f;
    #pragma unroll
    for (int w = 0; w < 8; ++w) {
        s0 += sred[w * 512 + i0];
        s1 += sred[w * 512 + i1];
    }
    __syncthreads();
    sred[i0] = s0;
    sred[i1] = s1;
    __syncthreads();

    // finalize: threads 0..127 each own one pixel of the tile
    if (threadIdx.x < 128) {
        const int p = threadIdx.x;        // = l*4 + j
        const int l = p >> 2;
        const int j = p & 3;
        const float r = sred[l * 16 +  0 + j];
        const float g = sred[l * 16 +  4 + j];
        const float b = sred[l * 16 +  8 + j];
        const float a = sred[l * 16 + 12 + j];
        const float inv = 1.0f / fmaxf(a, 1e-8f);
        const int ppx = x0 + (l & 3) * 4 + j;
        const int ppy = y0 + (l >> 2);
        const int pp  = ppy * IMG_W + ppx;
        if (pp < P) {
            out[3*pp + 0] = __saturatef(r * inv);
            out[3*pp + 1] = __saturatef(g * inv);
            out[3*pp + 2] = __saturatef(b * inv);
        }
    }
}

// ---------------------------------------------------------------- launch
extern "C" void kernel_launch(void* const* d_in, const int* in_sizes, int n_in,
                              void* d_out, int out_size) {
    const float* pos = (const float*)d_in[1];
    const float* lsc = (const float*)d_in[2];
    const float* col = (const float*)d_in[3];
    const float* lop = (const float*)d_in[4];
    float* out = (float*)d_out;

    int N = in_sizes[1] / 2;
    int P = out_size / 3;
    if (N > MAX_N) N = MAX_N;

    const int bin_threads = N * 32;                       // one warp per gaussian
    fg_bin<<<(bin_threads + 255) / 256, 256>>>(pos, lsc, col, lop, N);
    fg_render<<<NTILES, 256>>>(out, P);
}

// round 12
// speedup vs baseline: 1.0078x; 1.0026x over previous
#include <cuda_runtime.h>
#include <cuda_bf16.h>
#include <cstdint>

// FastGaussian2D: tile-binned 2D gaussian splat render.
// P pixels (256x256 = 512 tiles of 16x8), N=2048 gaussians.
// out[p] = clip(sum_n alpha*color / max(sum alpha,1e-8), 0, 1)
//
// R12 (= R11 + missing <cstdint>): cp.async double-buffered smem staging of
// the per-tile payload lists. The render loop reads payloads via LDS (29 cyc,
// hidden) instead of per-warp LDG chains whose L2 latency could not be hidden
// under the 64-reg cap.
//
// Two launches:
//   fg_bin:    warp per gaussian; conservative ellipse cull; appends packed
//              render-ready payloads into per-tile lists.
//   fg_render: block per tile; 128-entry windows staged to smem via cp.async
//              (double buffered); 8 warps stride each window; f32x2 packed
//              eval + ex2.approx; block smem reduction; finalize + write
//              d_out directly; re-zeroes its tile counter for graph replay.
//
// Cull safety: dropped per-pixel alpha <= N * w_max * 2^-40 ~ 3e-10 absolute.

#define IMG_W 256
#define TILE_W 16
#define TILE_H 8
#define NTILES_X 16
#define NTILES_Y 32
#define NTILES 512
#define MAX_N 2048
#define WIN 128
#define LOG2E 1.4426950408889634f
#define PI_F  3.14159265358979323846f
#define THR_LOG2 -40.0f

typedef unsigned long long ull;

__device__ int        g_counts[NTILES];          // zero-init; re-zeroed by render
__device__ ulonglong2 gP0 [NTILES * MAX_N];      // {(-px,-px), (naxl,naxl)}
__device__ ulonglong2 gW12[NTILES * MAX_N];      // {(wr,wr), (wg,wg)}
__device__ ulonglong2 gW34[NTILES * MAX_N];      // {(wb,wb), (wa,wa)}
__device__ float2     gPY [NTILES * MAX_N];      // {py, nayl}

__device__ __forceinline__ ull packf(float a, float b) {
    return (ull)__float_as_uint(a) | ((ull)__float_as_uint(b) << 32);
}
__device__ __forceinline__ float lowf(ull v)  { return __uint_as_float((unsigned)v); }
__device__ __forceinline__ float highf(ull v) { return __uint_as_float((unsigned)(v >> 32)); }

__device__ __forceinline__ ull add2(ull a, ull b) {
    ull d; asm("add.rn.f32x2 %0, %1, %2;" : "=l"(d) : "l"(a), "l"(b)); return d;
}
__device__ __forceinline__ ull mul2(ull a, ull b) {
    ull d; asm("mul.rn.f32x2 %0, %1, %2;" : "=l"(d) : "l"(a), "l"(b)); return d;
}
__device__ __forceinline__ ull fma2(ull a, ull b, ull c) {
    ull d; asm("fma.rn.f32x2 %0, %1, %2, %3;" : "=l"(d) : "l"(a), "l"(b), "l"(c)); return d;
}
__device__ __forceinline__ float ex2f(float x) {
    float y; asm("ex2.approx.ftz.f32 %0, %1;" : "=f"(y) : "f"(x)); return y;
}
__device__ __forceinline__ uint32_t s2u(const void* p) {
    return (uint32_t)__cvta_generic_to_shared(p);
}
__device__ __forceinline__ void cpa16(uint32_t dst, const void* src) {
    asm volatile("cp.async.ca.shared.global [%0], [%1], 16;" :: "r"(dst), "l"(src));
}
__device__ __forceinline__ void cpa8(uint32_t dst, const void* src) {
    asm volatile("cp.async.ca.shared.global [%0], [%1], 8;" :: "r"(dst), "l"(src));
}

// ---------------------------------------------------------------- bin
__global__ void fg_bin(const float* __restrict__ pos,
                       const float* __restrict__ lsc,
                       const float* __restrict__ col,
                       const float* __restrict__ lop, int N) {
    const int g    = (blockIdx.x * blockDim.x + threadIdx.x) >> 5;
    const int lane = threadIdx.x & 31;
    if (g >= N) return;

    const float px = pos[2*g], py = pos[2*g+1];
    const float sx = fmaxf(expf(lsc[2*g]),   0.1f);
    const float sy = fmaxf(expf(lsc[2*g+1]), 0.1f);
    const float opac = expf(lop[g]);
    const float c = opac / (2.0f * PI_F * sx * sy);
    const float naxl = -0.5f * LOG2E / (sx * sx);
    const float nayl = -0.5f * LOG2E / (sy * sy);

    const ulonglong2 P0  = make_ulonglong2(packf(-px, -px), packf(naxl, naxl));
    const float wr = c * col[3*g], wg = c * col[3*g+1], wb = c * col[3*g+2];
    const ulonglong2 W12 = make_ulonglong2(packf(wr, wr), packf(wg, wg));
    const ulonglong2 W34 = make_ulonglong2(packf(wb, wb), packf(c,  c));
    const float2 PY = make_float2(py, nayl);

    const float rx = sqrtf(THR_LOG2 / naxl);
    const float ry = sqrtf(THR_LOG2 / nayl);

    int tx0 = max(0,            (int)floorf((px - rx) * (1.0f/TILE_W)));
    int tx1 = min(NTILES_X - 1, (int)floorf((px + rx) * (1.0f/TILE_W)));
    int ty0 = max(0,            (int)floorf((py - ry) * (1.0f/TILE_H)));
    int ty1 = min(NTILES_Y - 1, (int)floorf((py + ry) * (1.0f/TILE_H)));
    if (tx1 < tx0 || ty1 < ty0) return;

    const int wbb = tx1 - tx0 + 1;
    const int nt  = wbb * (ty1 - ty0 + 1);

    for (int i = lane; i < nt; i += 32) {
        const int tx = tx0 + i % wbb;
        const int ty = ty0 + i / wbb;
        const float mx = fmaxf(fabsf((float)(tx * TILE_W) + 7.5f - px) - 7.5f, 0.0f);
        const float my = fmaxf(fabsf((float)(ty * TILE_H) + 3.5f - py) - 3.5f, 0.0f);
        if (naxl * (mx * mx) + nayl * (my * my) >= THR_LOG2) {
            const int t = ty * NTILES_X + tx;
            const int slot = atomicAdd(&g_counts[t], 1);   // slot < N by construction
            const int idx = t * MAX_N + slot;
            gP0 [idx] = P0;
            gW12[idx] = W12;
            gW34[idx] = W34;
            gPY [idx] = PY;
        }
    }
}

// ---------------------------------------------------------------- render
__global__ void __launch_bounds__(256, 4)
fg_render(float* __restrict__ out, int P) {
    __shared__ ulonglong2 sP0 [2][WIN];
    __shared__ ulonglong2 sW12[2][WIN];
    __shared__ ulonglong2 sW34[2][WIN];
    __shared__ float2     sPY [2][WIN];
    __shared__ float      sred[8 * 512];   // 16 KB

    const int tile = blockIdx.x;
    const int warp = threadIdx.x >> 5;
    const int lane = threadIdx.x & 31;
    const int tid  = threadIdx.x;

    const int x0 = (tile & (NTILES_X - 1)) * TILE_W;
    const int y0 = (tile >> 4) * TILE_H;

    const float cy = (float)(y0 + (lane >> 2));
    const float xf = (float)(x0 + (lane & 3) * 4);
    const ull cx0 = packf(xf,        xf + 1.0f);
    const ull cx1 = packf(xf + 2.0f, xf + 3.0f);

    const int count = g_counts[tile];
    const int base  = tile * MAX_N;
    const int nwin  = (count + WIN - 1) / WIN;

    __syncthreads();                       // everyone has read count
    if (tid == 0) g_counts[tile] = 0;      // restore invariant for next replay

    // cooperative async window copy (coalesced 16B/8B per thread)
    auto copy_win = [&](int b, int w) {
        const int wsz  = min(WIN, count - w * WIN);
        const int gb   = base + w * WIN;
        if (tid < WIN) {
            if (tid < wsz) {
                cpa16(s2u(&sP0 [b][tid]), &gP0 [gb + tid]);
                cpa16(s2u(&sW34[b][tid]), &gW34[gb + tid]);
            }
        } else {
            const int u = tid - WIN;
            if (u < wsz) {
                cpa16(s2u(&sW12[b][u]), &gW12[gb + u]);
                cpa8 (s2u(&sPY [b][u]), &gPY [gb + u]);
            }
        }
    };

    ull aR0 = 0, aR1 = 0, aG0 = 0, aG1 = 0;
    ull aB0 = 0, aB1 = 0, aA0 = 0, aA1 = 0;

    if (nwin > 0) {
        copy_win(0, 0);
        asm volatile("cp.async.commit_group;");
    }

    for (int w = 0; w < nwin; ++w) {
        const int b = w & 1;
        if (w + 1 < nwin) {
            copy_win((w + 1) & 1, w + 1);
            asm volatile("cp.async.commit_group;");
            asm volatile("cp.async.wait_group 1;");
        } else {
            asm volatile("cp.async.wait_group 0;");
        }
        __syncthreads();

        const int wsz = min(WIN, count - w * WIN);
        #pragma unroll 2
        for (int k = warp; k < wsz; k += 8) {
            const ulonglong2 c1  = sP0 [b][k];   // (-px,-px), (naxl,naxl)
            const float2     yv  = sPY [b][k];   // py, nayl
            const ulonglong2 w12 = sW12[b][k];   // (wr,wr), (wg,wg)
            const ulonglong2 w34 = sW34[b][k];   // (wb,wb), (wa,wa)

            const float dy = cy - yv.x;
            const float ey = (dy * dy) * yv.y;            // nayl*dy^2 (log2-scaled)
            const ull ey2 = packf(ey, ey);

            const ull d0 = add2(cx0, c1.x);               // dx
            const ull d1 = add2(cx1, c1.x);
            const ull e0 = fma2(mul2(d0, d0), c1.y, ey2); // naxl*dx^2 + ey
            const ull e1 = fma2(mul2(d1, d1), c1.y, ey2);

            const ull x0p = packf(ex2f(lowf(e0)), ex2f(highf(e0)));
            const ull x1p = packf(ex2f(lowf(e1)), ex2f(highf(e1)));

            aR0 = fma2(x0p, w12.x, aR0);  aR1 = fma2(x1p, w12.x, aR1);
            aG0 = fma2(x0p, w12.y, aG0);  aG1 = fma2(x1p, w12.y, aG1);
            aB0 = fma2(x0p, w34.x, aB0);  aB1 = fma2(x1p, w34.x, aB1);
            aA0 = fma2(x0p, w34.y, aA0);  aA1 = fma2(x1p, w34.y, aA1);
        }
        __syncthreads();
    }

    // per-lane layout k = c*4 + j : channel c in {R,G,B,A}, pixel j in 0..3
    float vals[16];
    vals[ 0] = lowf(aR0); vals[ 1] = highf(aR0); vals[ 2] = lowf(aR1); vals[ 3] = highf(aR1);
    vals[ 4] = lowf(aG0); vals[ 5] = highf(aG0); vals[ 6] = lowf(aG1); vals[ 7] = highf(aG1);
    vals[ 8] = lowf(aB0); vals[ 9] = highf(aB0); vals[10] = lowf(aB1); vals[11] = highf(aB1);
    vals[12] = lowf(aA0); vals[13] = highf(aA0); vals[14] = lowf(aA1); vals[15] = highf(aA1);

    float* dst = &sred[warp * 512 + lane * 16];
    #pragma unroll
    for (int k = 0; k < 16; ++k) dst[k] = vals[k];
    __syncthreads();

    // reduce 8 warp-copies of 512 floats: each thread sums 2 slots
    const int i0 = tid;
    const int i1 = tid + 256;
    float s0 = 0.f, s1 = 0.f;
    #pragma unroll
    for (int w = 0; w < 8; ++w) {
        s0 += sred[w * 512 + i0];
        s1 += sred[w * 512 + i1];
    }
    __syncthreads();
    sred[i0] = s0;
    sred[i1] = s1;
    __syncthreads();

    // finalize: threads 0..127 each own one pixel of the tile
    if (tid < 128) {
        const int p = tid;                // = l*4 + j
        const int l = p >> 2;
        const int j = p & 3;
        const float r = sred[l * 16 +  0 + j];
        const float g = sred[l * 16 +  4 + j];
        const float b = sred[l * 16 +  8 + j];
        const float a = sred[l * 16 + 12 + j];
        const float inv = 1.0f / fmaxf(a, 1e-8f);
        const int ppx = x0 + (l & 3) * 4 + j;
        const int ppy = y0 + (l >> 2);
        const int pp  = ppy * IMG_W + ppx;
        if (pp < P) {
            out[3*pp + 0] = __saturatef(r * inv);
            out[3*pp + 1] = __saturatef(g * inv);
            out[3*pp + 2] = __saturatef(b * inv);
        }
    }
}

// ---------------------------------------------------------------- launch
extern "C" void kernel_launch(void* const* d_in, const int* in_sizes, int n_in,
                              void* d_out, int out_size) {
    const float* pos = (const float*)d_in[1];
    const float* lsc = (const float*)d_in[2];
    const float* col = (const float*)d_in[3];
    const float* lop = (const float*)d_in[4];
    float* out = (float*)d_out;

    int N = in_sizes[1] / 2;
    int P = out_size / 3;
    if (N > MAX_N) N = MAX_N;

    const int bin_threads = N * 32;                       // one warp per gaussian
    fg_bin<<<(bin_threads + 255) / 256, 256>>>(pos, lsc, col, lop, N);
    fg_render<<<NTILES, 256>>>(out, P);
}

// round 13
// speedup vs baseline: 1.1183x; 1.1097x over previous
#include <cuda_runtime.h>
#include <cuda_bf16.h>
#include <cstdint>

// FastGaussian2D: tile-binned 2D gaussian splat render.
// P pixels (256x256 = 512 tiles of 16x8), N=2048 gaussians.
// out[p] = clip(sum_n alpha*color / max(sum alpha,1e-8), 0, 1)
//
// R13: SEPARABLE exponential. exp(a*dx^2 + b*dy^2) = exp(a*dx^2)*exp(b*dy^2):
// per (gaussian, tile) only 16 x-basis + 8 y-basis exps exist. One warp-wide
// ex2 computes all 24 in a single MUFU op (lanes 0-15 -> ex, 16-23 -> ey),
// shfl distributes, pixels just multiply. 4x fewer MUFU ops than R12 (MUFU
// was co-binding at ~10.4k cyc/SM). Payload shrinks to 48B; THR -40 -> -28.
//
// Two launches:
//   fg_bin:    warp per gaussian; conservative ellipse cull; appends payloads
//              {A=px,py,naxl,nayl} + packed W12/W34 into per-tile lists.
//   fg_render: block per tile; 128-entry windows staged to smem via cp.async
//              (double buffered); separable eval; block smem reduction;
//              finalize + write d_out; re-zeroes tile counter for replay.
//
// Cull safety: dropped per-pixel alpha <= ~1e-6 absolute vs total alpha
// >= ~1e-3 -> relative impact <= ~1e-5, far below the 1e-3 gate.

#define IMG_W 256
#define TILE_W 16
#define TILE_H 8
#define NTILES_X 16
#define NTILES_Y 32
#define NTILES 512
#define MAX_N 2048
#define WIN 128
#define LOG2E 1.4426950408889634f
#define PI_F  3.14159265358979323846f
#define THR_LOG2 -28.0f

typedef unsigned long long ull;

__device__ int        g_counts[NTILES];          // zero-init; re-zeroed by render
__device__ float4     gA  [NTILES * MAX_N];      // {px, py, naxl, nayl}
__device__ ulonglong2 gW12[NTILES * MAX_N];      // {(wr,wr), (wg,wg)}
__device__ ulonglong2 gW34[NTILES * MAX_N];      // {(wb,wb), (wa,wa)}

__device__ __forceinline__ ull packf(float a, float b) {
    return (ull)__float_as_uint(a) | ((ull)__float_as_uint(b) << 32);
}
__device__ __forceinline__ float lowf(ull v)  { return __uint_as_float((unsigned)v); }
__device__ __forceinline__ float highf(ull v) { return __uint_as_float((unsigned)(v >> 32)); }

__device__ __forceinline__ ull mul2(ull a, ull b) {
    ull d; asm("mul.rn.f32x2 %0, %1, %2;" : "=l"(d) : "l"(a), "l"(b)); return d;
}
__device__ __forceinline__ ull fma2(ull a, ull b, ull c) {
    ull d; asm("fma.rn.f32x2 %0, %1, %2, %3;" : "=l"(d) : "l"(a), "l"(b), "l"(c)); return d;
}
__device__ __forceinline__ float ex2f(float x) {
    float y; asm("ex2.approx.ftz.f32 %0, %1;" : "=f"(y) : "f"(x)); return y;
}
__device__ __forceinline__ uint32_t s2u(const void* p) {
    return (uint32_t)__cvta_generic_to_shared(p);
}
__device__ __forceinline__ void cpa16(uint32_t dst, const void* src) {
    asm volatile("cp.async.ca.shared.global [%0], [%1], 16;" :: "r"(dst), "l"(src));
}

// ---------------------------------------------------------------- bin
__global__ void fg_bin(const float* __restrict__ pos,
                       const float* __restrict__ lsc,
                       const float* __restrict__ col,
                       const float* __restrict__ lop, int N) {
    const int g    = (blockIdx.x * blockDim.x + threadIdx.x) >> 5;
    const int lane = threadIdx.x & 31;
    if (g >= N) return;

    const float px = pos[2*g], py = pos[2*g+1];
    const float sx = fmaxf(expf(lsc[2*g]),   0.1f);
    const float sy = fmaxf(expf(lsc[2*g+1]), 0.1f);
    const float opac = expf(lop[g]);
    const float c = opac / (2.0f * PI_F * sx * sy);
    const float naxl = -0.5f * LOG2E / (sx * sx);
    const float nayl = -0.5f * LOG2E / (sy * sy);

    const float4 A = make_float4(px, py, naxl, nayl);
    const float wr = c * col[3*g], wg = c * col[3*g+1], wb = c * col[3*g+2];
    const ulonglong2 W12 = make_ulonglong2(packf(wr, wr), packf(wg, wg));
    const ulonglong2 W34 = make_ulonglong2(packf(wb, wb), packf(c,  c));

    const float rx = sqrtf(THR_LOG2 / naxl);
    const float ry = sqrtf(THR_LOG2 / nayl);

    int tx0 = max(0,            (int)floorf((px - rx) * (1.0f/TILE_W)));
    int tx1 = min(NTILES_X - 1, (int)floorf((px + rx) * (1.0f/TILE_W)));
    int ty0 = max(0,            (int)floorf((py - ry) * (1.0f/TILE_H)));
    int ty1 = min(NTILES_Y - 1, (int)floorf((py + ry) * (1.0f/TILE_H)));
    if (tx1 < tx0 || ty1 < ty0) return;

    const int wbb = tx1 - tx0 + 1;
    const int nt  = wbb * (ty1 - ty0 + 1);

    for (int i = lane; i < nt; i += 32) {
        const int tx = tx0 + i % wbb;
        const int ty = ty0 + i / wbb;
        const float mx = fmaxf(fabsf((float)(tx * TILE_W) + 7.5f - px) - 7.5f, 0.0f);
        const float my = fmaxf(fabsf((float)(ty * TILE_H) + 3.5f - py) - 3.5f, 0.0f);
        if (naxl * (mx * mx) + nayl * (my * my) >= THR_LOG2) {
            const int t = ty * NTILES_X + tx;
            const int slot = atomicAdd(&g_counts[t], 1);   // slot < N by construction
            const int idx = t * MAX_N + slot;
            gA  [idx] = A;
            gW12[idx] = W12;
            gW34[idx] = W34;
        }
    }
}

// ---------------------------------------------------------------- render
__global__ void __launch_bounds__(256, 4)
fg_render(float* __restrict__ out, int P) {
    __shared__ float4     sA  [2][WIN];
    __shared__ ulonglong2 sW12[2][WIN];
    __shared__ ulonglong2 sW34[2][WIN];
    __shared__ float      sred[8 * 512];   // 16 KB

    const int tile = blockIdx.x;
    const int warp = threadIdx.x >> 5;
    const int lane = threadIdx.x & 31;
    const int tid  = threadIdx.x;

    const int x0 = (tile & (NTILES_X - 1)) * TILE_W;
    const int y0 = (tile >> 4) * TILE_H;

    // separable basis assignment:
    //  lanes 0-15  : ex for x = x0 + lane
    //  lanes 16-23 : ey for y = y0 + (lane-16)
    //  lanes 24-31 : harmless duplicate work (results unused)
    const bool isX  = (lane < 16);
    const float u   = isX ? (float)(x0 + lane) : (float)(y0 + (lane & 7));
    const int rowSh = 16 + (lane >> 2);      // shfl src for my row's ey
    const int xg4   = (lane & 3) * 4;        // shfl src base for my 4 ex's

    const int count = g_counts[tile];
    const int base  = tile * MAX_N;
    const int nwin  = (count + WIN - 1) / WIN;

    __syncthreads();                       // everyone has read count
    if (tid == 0) g_counts[tile] = 0;      // restore invariant for next replay

    // cooperative async window copy (coalesced 16B per thread)
    auto copy_win = [&](int b, int w) {
        const int wsz = min(WIN, count - w * WIN);
        const int gb  = base + w * WIN;
        if (tid < WIN) {
            if (tid < wsz) cpa16(s2u(&sA[b][tid]), &gA[gb + tid]);
        } else {
            const int uu = tid - WIN;
            if (uu < wsz) {
                cpa16(s2u(&sW12[b][uu]), &gW12[gb + uu]);
                cpa16(s2u(&sW34[b][uu]), &gW34[gb + uu]);
            }
        }
    };

    ull aR0 = 0, aR1 = 0, aG0 = 0, aG1 = 0;
    ull aB0 = 0, aB1 = 0, aA0 = 0, aA1 = 0;

    if (nwin > 0) {
        copy_win(0, 0);
        asm volatile("cp.async.commit_group;");
    }

    for (int w = 0; w < nwin; ++w) {
        const int b = w & 1;
        if (w + 1 < nwin) {
            copy_win((w + 1) & 1, w + 1);
            asm volatile("cp.async.commit_group;");
            asm volatile("cp.async.wait_group 1;");
        } else {
            asm volatile("cp.async.wait_group 0;");
        }
        __syncthreads();

        const int wsz = min(WIN, count - w * WIN);
        #pragma unroll 2
        for (int k = warp; k < wsz; k += 8) {
            const float4 A = sA[b][k];      // px, py, naxl, nayl

            // one warp-wide ex2 evaluates all 16 ex + 8 ey basis values
            const float ctr  = isX ? A.x : A.y;
            const float coef = isX ? A.z : A.w;
            const float d    = u - ctr;
            const float v    = ex2f(coef * (d * d));   // in (0,1]

            const float ey = __shfl_sync(0xFFFFFFFFu, v, rowSh);
            const float e0 = __shfl_sync(0xFFFFFFFFu, v, xg4 + 0);
            const float e1 = __shfl_sync(0xFFFFFFFFu, v, xg4 + 1);
            const float e2 = __shfl_sync(0xFFFFFFFFu, v, xg4 + 2);
            const float e3 = __shfl_sync(0xFFFFFFFFu, v, xg4 + 3);

            const ull ey2v = packf(ey, ey);
            const ull exy0 = mul2(packf(e0, e1), ey2v);   // alpha/w for px 0,1
            const ull exy1 = mul2(packf(e2, e3), ey2v);   // alpha/w for px 2,3

            const ulonglong2 w12 = sW12[b][k];   // (wr,wr), (wg,wg)
            const ulonglong2 w34 = sW34[b][k];   // (wb,wb), (wa,wa)

            aR0 = fma2(exy0, w12.x, aR0);  aR1 = fma2(exy1, w12.x, aR1);
            aG0 = fma2(exy0, w12.y, aG0);  aG1 = fma2(exy1, w12.y, aG1);
            aB0 = fma2(exy0, w34.x, aB0);  aB1 = fma2(exy1, w34.x, aB1);
            aA0 = fma2(exy0, w34.y, aA0);  aA1 = fma2(exy1, w34.y, aA1);
        }
        __syncthreads();
    }

    // per-lane layout k = c*4 + j : channel c in {R,G,B,A}, pixel j in 0..3
    float vals[16];
    vals[ 0] = lowf(aR0); vals[ 1] = highf(aR0); vals[ 2] = lowf(aR1); vals[ 3] = highf(aR1);
    vals[ 4] = lowf(aG0); vals[ 5] = highf(aG0); vals[ 6] = lowf(aG1); vals[ 7] = highf(aG1);
    vals[ 8] = lowf(aB0); vals[ 9] = highf(aB0); vals[10] = lowf(aB1); vals[11] = highf(aB1);
    vals[12] = lowf(aA0); vals[13] = highf(aA0); vals[14] = lowf(aA1); vals[15] = highf(aA1);

    float* dst = &sred[warp * 512 + lane * 16];
    #pragma unroll
    for (int k = 0; k < 16; ++k) dst[k] = vals[k];
    __syncthreads();

    // reduce 8 warp-copies of 512 floats: each thread sums 2 slots
    const int i0 = tid;
    const int i1 = tid + 256;
    float s0 = 0.f, s1 = 0.f;
    #pragma unroll
    for (int w = 0; w < 8; ++w) {
        s0 += sred[w * 512 + i0];
        s1 += sred[w * 512 + i1];
    }
    __syncthreads();
    sred[i0] = s0;
    sred[i1] = s1;
    __syncthreads();

    // finalize: threads 0..127 each own one pixel of the tile
    if (tid < 128) {
        const int p = tid;                // = l*4 + j
        const int l = p >> 2;
        const int j = p & 3;
        const float r = sred[l * 16 +  0 + j];
        const float g = sred[l * 16 +  4 + j];
        const float b = sred[l * 16 +  8 + j];
        const float a = sred[l * 16 + 12 + j];
        const float inv = 1.0f / fmaxf(a, 1e-8f);
        const int ppx = x0 + (l & 3) * 4 + j;
        const int ppy = y0 + (l >> 2);
        const int pp  = ppy * IMG_W + ppx;
        if (pp < P) {
            out[3*pp + 0] = __saturatef(r * inv);
            out[3*pp + 1] = __saturatef(g * inv);
            out[3*pp + 2] = __saturatef(b * inv);
        }
    }
}

// ---------------------------------------------------------------- launch
extern "C" void kernel_launch(void* const* d_in, const int* in_sizes, int n_in,
                              void* d_out, int out_size) {
    const float* pos = (const float*)d_in[1];
    const float* lsc = (const float*)d_in[2];
    const float* col = (const float*)d_in[3];
    const float* lop = (const float*)d_in[4];
    float* out = (float*)d_out;

    int N = in_sizes[1] / 2;
    int P = out_size / 3;
    if (N > MAX_N) N = MAX_N;

    const int bin_threads = N * 32;                       // one warp per gaussian
    fg_bin<<<(bin_threads + 255) / 256, 256>>>(pos, lsc, col, lop, N);
    fg_render<<<NTILES, 256>>>(out, P);
}

// round 15
// speedup vs baseline: 1.1923x; 1.0662x over previous
#include <cuda_runtime.h>
#include <cuda_bf16.h>
#include <cstdint>

// FastGaussian2D: tile-binned 2D gaussian splat render.
// P pixels (256x256 = 512 tiles of 16x8), N=2048 gaussians.
// out[p] = clip(sum_n alpha*color / max(sum alpha,1e-8), 0, 1)
//
// R15 (= R14 resubmitted after infra failure): WARP-PRIVATE cp.async staging.
// Each warp owns a contiguous 1/8 slice of its tile's list and double-buffers
// 32-entry windows in its own smem region; synchronization is
// cp.async.wait_group + __syncwarp only. No __syncthreads in the hot loop ->
// warps desynchronize and cover each other's LDS/SHFL/EX2 latency chains
// (R13 stalled at issue=42% because the block-wide window barrier re-locked
// all 8 warps every 16 iterations).
//
// Eval: separable exponential (one warp-wide ex2 computes the 16 x-basis +
// 8 y-basis values; shfl distributes; pixels just multiply). f32x2 packed
// accumulate. Block smem reduction + direct finalize into d_out.
//
// Cull safety: dropped per-pixel alpha <= ~1.2e-6 absolute vs total alpha
// >= ~1e-2 -> relative impact ~1e-4, below the 1e-3 gate with margin.

#define IMG_W 256
#define TILE_W 16
#define TILE_H 8
#define NTILES_X 16
#define NTILES_Y 32
#define NTILES 512
#define MAX_N 2048
#define WIN 32
#define LOG2E 1.4426950408889634f
#define PI_F  3.14159265358979323846f
#define THR_LOG2 -28.0f

typedef unsigned long long ull;

__device__ int        g_counts[NTILES];          // zero-init; re-zeroed by render
__device__ float4     gA  [NTILES * MAX_N];      // {px, py, naxl, nayl}
__device__ ulonglong2 gW12[NTILES * MAX_N];      // {(wr,wr), (wg,wg)}
__device__ ulonglong2 gW34[NTILES * MAX_N];      // {(wb,wb), (wa,wa)}

__device__ __forceinline__ ull packf(float a, float b) {
    return (ull)__float_as_uint(a) | ((ull)__float_as_uint(b) << 32);
}
__device__ __forceinline__ float lowf(ull v)  { return __uint_as_float((unsigned)v); }
__device__ __forceinline__ float highf(ull v) { return __uint_as_float((unsigned)(v >> 32)); }

__device__ __forceinline__ ull mul2(ull a, ull b) {
    ull d; asm("mul.rn.f32x2 %0, %1, %2;" : "=l"(d) : "l"(a), "l"(b)); return d;
}
__device__ __forceinline__ ull fma2(ull a, ull b, ull c) {
    ull d; asm("fma.rn.f32x2 %0, %1, %2, %3;" : "=l"(d) : "l"(a), "l"(b), "l"(c)); return d;
}
__device__ __forceinline__ float ex2f(float x) {
    float y; asm("ex2.approx.ftz.f32 %0, %1;" : "=f"(y) : "f"(x)); return y;
}
__device__ __forceinline__ uint32_t s2u(const void* p) {
    return (uint32_t)__cvta_generic_to_shared(p);
}
__device__ __forceinline__ void cpa16(uint32_t dst, const void* src) {
    asm volatile("cp.async.ca.shared.global [%0], [%1], 16;" :: "r"(dst), "l"(src));
}

// ---------------------------------------------------------------- bin
__global__ void fg_bin(const float* __restrict__ pos,
                       const float* __restrict__ lsc,
                       const float* __restrict__ col,
                       const float* __restrict__ lop, int N) {
    const int g    = (blockIdx.x * blockDim.x + threadIdx.x) >> 5;
    const int lane = threadIdx.x & 31;
    if (g >= N) return;

    const float px = pos[2*g], py = pos[2*g+1];
    const float sx = fmaxf(expf(lsc[2*g]),   0.1f);
    const float sy = fmaxf(expf(lsc[2*g+1]), 0.1f);
    const float opac = expf(lop[g]);
    const float c = opac / (2.0f * PI_F * sx * sy);
    const float naxl = -0.5f * LOG2E / (sx * sx);
    const float nayl = -0.5f * LOG2E / (sy * sy);

    const float4 A = make_float4(px, py, naxl, nayl);
    const float wr = c * col[3*g], wg = c * col[3*g+1], wb = c * col[3*g+2];
    const ulonglong2 W12 = make_ulonglong2(packf(wr, wr), packf(wg, wg));
    const ulonglong2 W34 = make_ulonglong2(packf(wb, wb), packf(c,  c));

    const float rx = sqrtf(THR_LOG2 / naxl);
    const float ry = sqrtf(THR_LOG2 / nayl);

    int tx0 = max(0,            (int)floorf((px - rx) * (1.0f/TILE_W)));
    int tx1 = min(NTILES_X - 1, (int)floorf((px + rx) * (1.0f/TILE_W)));
    int ty0 = max(0,            (int)floorf((py - ry) * (1.0f/TILE_H)));
    int ty1 = min(NTILES_Y - 1, (int)floorf((py + ry) * (1.0f/TILE_H)));
    if (tx1 < tx0 || ty1 < ty0) return;

    const int wbb = tx1 - tx0 + 1;
    const int nt  = wbb * (ty1 - ty0 + 1);

    for (int i = lane; i < nt; i += 32) {
        const int tx = tx0 + i % wbb;
        const int ty = ty0 + i / wbb;
        const float mx = fmaxf(fabsf((float)(tx * TILE_W) + 7.5f - px) - 7.5f, 0.0f);
        const float my = fmaxf(fabsf((float)(ty * TILE_H) + 3.5f - py) - 3.5f, 0.0f);
        if (naxl * (mx * mx) + nayl * (my * my) >= THR_LOG2) {
            const int t = ty * NTILES_X + tx;
            const int slot = atomicAdd(&g_counts[t], 1);   // slot < N by construction
            const int idx = t * MAX_N + slot;
            gA  [idx] = A;
            gW12[idx] = W12;
            gW34[idx] = W34;
        }
    }
}

// ---------------------------------------------------------------- render
__global__ void __launch_bounds__(256, 4)
fg_render(float* __restrict__ out, int P) {
    __shared__ float4     sA  [8][2][WIN];   //  8 KB
    __shared__ ulonglong2 sW12[8][2][WIN];   //  8 KB
    __shared__ ulonglong2 sW34[8][2][WIN];   //  8 KB
    __shared__ float      sred[8 * 512];     // 16 KB

    const int tile = blockIdx.x;
    const int warp = threadIdx.x >> 5;
    const int lane = threadIdx.x & 31;
    const int tid  = threadIdx.x;

    const int x0 = (tile & (NTILES_X - 1)) * TILE_W;
    const int y0 = (tile >> 4) * TILE_H;

    // separable basis assignment:
    //  lanes 0-15  : ex for x = x0 + lane
    //  lanes 16-23 : ey for y = y0 + (lane-16)
    //  lanes 24-31 : harmless duplicate work (results unused)
    const bool isX  = (lane < 16);
    const float u   = isX ? (float)(x0 + lane) : (float)(y0 + (lane & 7));
    const int rowSh = 16 + (lane >> 2);      // shfl src for my row's ey
    const int xg4   = (lane & 3) * 4;        // shfl src base for my 4 ex's

    const int count = g_counts[tile];
    const int base  = tile * MAX_N;

    __syncthreads();                       // everyone has read count
    if (tid == 0) g_counts[tile] = 0;      // restore invariant for next replay

    // contiguous per-warp slice, staged warp-privately
    const int s0   = (count *  warp     ) >> 3;
    const int s1   = (count * (warp + 1)) >> 3;
    const int len  = s1 - s0;
    const int nwin = (len + WIN - 1) / WIN;
    const int gb0  = base + s0;

    // per-warp async window copy: lane i copies entry (w*WIN + i), 3x 16B
    auto copy_win = [&](int b, int w) {
        const int e = w * WIN + lane;
        if (e < len) {
            cpa16(s2u(&sA  [warp][b][lane]), &gA  [gb0 + e]);
            cpa16(s2u(&sW12[warp][b][lane]), &gW12[gb0 + e]);
            cpa16(s2u(&sW34[warp][b][lane]), &gW34[gb0 + e]);
        }
        asm volatile("cp.async.commit_group;");
    };

    ull aR0 = 0, aR1 = 0, aG0 = 0, aG1 = 0;
    ull aB0 = 0, aB1 = 0, aA0 = 0, aA1 = 0;

    if (nwin > 0) copy_win(0, 0);

    for (int w = 0; w < nwin; ++w) {
        const int b = w & 1;
        if (w + 1 < nwin) {
            copy_win((w + 1) & 1, w + 1);
            asm volatile("cp.async.wait_group 1;");
        } else {
            asm volatile("cp.async.wait_group 0;");
        }
        __syncwarp();

        const int wsz = min(WIN, len - w * WIN);
        #pragma unroll 4
        for (int k = 0; k < wsz; ++k) {
            const float4 A = sA[warp][b][k];      // px, py, naxl, nayl

            // one warp-wide ex2 evaluates all 16 ex + 8 ey basis values
            const float ctr  = isX ? A.x : A.y;
            const float coef = isX ? A.z : A.w;
            const float d    = u - ctr;
            const float v    = ex2f(coef * (d * d));   // in (0,1]

            const float ey = __shfl_sync(0xFFFFFFFFu, v, rowSh);
            const float e0 = __shfl_sync(0xFFFFFFFFu, v, xg4 + 0);
            const float e1 = __shfl_sync(0xFFFFFFFFu, v, xg4 + 1);
            const float e2 = __shfl_sync(0xFFFFFFFFu, v, xg4 + 2);
            const float e3 = __shfl_sync(0xFFFFFFFFu, v, xg4 + 3);

            const ull ey2v = packf(ey, ey);
            const ull exy0 = mul2(packf(e0, e1), ey2v);   // alpha/w for px 0,1
            const ull exy1 = mul2(packf(e2, e3), ey2v);   // alpha/w for px 2,3

            const ulonglong2 w12 = sW12[warp][b][k];   // (wr,wr), (wg,wg)
            const ulonglong2 w34 = sW34[warp][b][k];   // (wb,wb), (wa,wa)

            aR0 = fma2(exy0, w12.x, aR0);  aR1 = fma2(exy1, w12.x, aR1);
            aG0 = fma2(exy0, w12.y, aG0);  aG1 = fma2(exy1, w12.y, aG1);
            aB0 = fma2(exy0, w34.x, aB0);  aB1 = fma2(exy1, w34.x, aB1);
            aA0 = fma2(exy0, w34.y, aA0);  aA1 = fma2(exy1, w34.y, aA1);
        }
        __syncwarp();
    }

    // per-lane layout k = c*4 + j : channel c in {R,G,B,A}, pixel j in 0..3
    float vals[16];
    vals[ 0] = lowf(aR0); vals[ 1] = highf(aR0); vals[ 2] = lowf(aR1); vals[ 3] = highf(aR1);
    vals[ 4] = lowf(aG0); vals[ 5] = highf(aG0); vals[ 6] = lowf(aG1); vals[ 7] = highf(aG1);
    vals[ 8] = lowf(aB0); vals[ 9] = highf(aB0); vals[10] = lowf(aB1); vals[11] = highf(aB1);
    vals[12] = lowf(aA0); vals[13] = highf(aA0); vals[14] = lowf(aA1); vals[15] = highf(aA1);

    float* dst = &sred[warp * 512 + lane * 16];
    #pragma unroll
    for (int k = 0; k < 16; ++k) dst[k] = vals[k];
    __syncthreads();

    // reduce 8 warp-copies of 512 floats: each thread sums 2 slots
    const int i0 = tid;
    const int i1 = tid + 256;
    float s0r = 0.f, s1r = 0.f;
    #pragma unroll
    for (int w = 0; w < 8; ++w) {
        s0r += sred[w * 512 + i0];
        s1r += sred[w * 512 + i1];
    }
    __syncthreads();
    sred[i0] = s0r;
    sred[i1] = s1r;
    __syncthreads();

    // finalize: threads 0..127 each own one pixel of the tile
    if (tid < 128) {
        const int p = tid;                // = l*4 + j
        const int l = p >> 2;
        const int j = p & 3;
        const float r = sred[l * 16 +  0 + j];
        const float g = sred[l * 16 +  4 + j];
        const float b = sred[l * 16 +  8 + j];
        const float a = sred[l * 16 + 12 + j];
        const float inv = 1.0f / fmaxf(a, 1e-8f);
        const int ppx = x0 + (l & 3) * 4 + j;
        const int ppy = y0 + (l >> 2);
        const int pp  = ppy * IMG_W + ppx;
        if (pp < P) {
            out[3*pp + 0] = __saturatef(r * inv);
            out[3*pp + 1] = __saturatef(g * inv);
            out[3*pp + 2] = __saturatef(b * inv);
        }
    }
}

// ---------------------------------------------------------------- launch
extern "C" void kernel_launch(void* const* d_in, const int* in_sizes, int n_in,
                              void* d_out, int out_size) {
    const float* pos = (const float*)d_in[1];
    const float* lsc = (const float*)d_in[2];
    const float* col = (const float*)d_in[3];
    const float* lop = (const float*)d_in[4];
    float* out = (float*)d_out;

    int N = in_sizes[1] / 2;
    int P = out_size / 3;
    if (N > MAX_N) N = MAX_N;

    const int bin_threads = N * 32;                       // one warp per gaussian
    fg_bin<<<(bin_threads + 255) / 256, 256>>>(pos, lsc, col, lop, N);
    fg_render<<<NTILES, 256>>>(out, P);
}